// round 10
// baseline (speedup 1.0000x reference)
#include <cuda_runtime.h>
#include <cuda_bf16.h>
#include <cstdint>

// YOLOv1 loss — single fused kernel:
//   R1's non-persistent LDG.128+STS streaming (best measured: ~37us)
//   + fence-free epilogue: relaxed fp64 RED partials + acq_rel counter,
//     last block applies lambdas and writes out[4]. No MEMBAR, no 2nd kernel.

#define NCELL  (16384 * 7 * 7)       // 802816
#define BLK    128
#define TILE   128                   // cells per block
#define NTILE  (NCELL / TILE)        // 6272
#define TFL    (TILE * 30)           // floats per tensor per tile (3840)
#define TF4    (TFL / 4)             // float4 per tensor per tile (960)

__device__ double g_acc[4] = {0.0, 0.0, 0.0, 0.0};   // cls, conf, cwh, noobj
__device__ unsigned int g_count = 0;

__global__ __launch_bounds__(BLK) void yolo_fused(const float* __restrict__ P,
                                                  const float* __restrict__ T,
                                                  float* __restrict__ out)
{
    __shared__ float SP[TFL];
    __shared__ float ST[TFL];
    const int tid = threadIdx.x;
    const float CELL = 1.0f / 7.0f;

    // ---- coalesced float4 staging (LDG.128 + STS.128), exactly R1's form ----
    const size_t base = (size_t)blockIdx.x * TFL;
    const float4* gp = (const float4*)(P + base);
    const float4* gt = (const float4*)(T + base);
    float4* sp4 = (float4*)SP;
    float4* st4 = (float4*)ST;
    #pragma unroll
    for (int i = 0; i < (TF4 + BLK - 1) / BLK; ++i) {
        int idx = tid + i * BLK;
        if (idx < TF4) { sp4[idx] = gp[idx]; st4[idx] = gt[idx]; }
    }
    __syncthreads();

    const float* p = SP + tid * 30;
    const float* t = ST + tid * 30;

    const float t0 = t[0], t1 = t[1], t2 = t[2], t3 = t[3], tc = t[4];

    // target corners — faithful to the reference's in-place bug:
    //   xy1 = xy*CELL - wh*0.5 ;  xy2 = xy1*CELL + wh*0.5
    const float twx = t2 * t2, twy = t3 * t3;
    const float tx1 = t0 * CELL - 0.5f * twx;
    const float ty1 = t1 * CELL - 0.5f * twy;
    const float tx2 = tx1 * CELL + 0.5f * twx;
    const float ty2 = ty1 * CELL + 0.5f * twy;
    const float area_t = (tx2 - tx1) * (ty2 - ty1);

    float iou0, iou1;
    #pragma unroll
    for (int b = 0; b < 2; ++b) {
        const float px = p[b * 5 + 0], py = p[b * 5 + 1];
        const float pw = p[b * 5 + 2], ph = p[b * 5 + 3];
        const float pwx = pw * pw, pwy = ph * ph;
        const float x1 = px * CELL - 0.5f * pwx;
        const float y1 = py * CELL - 0.5f * pwy;
        const float x2 = x1 * CELL + 0.5f * pwx;
        const float y2 = y1 * CELL + 0.5f * pwy;
        const float ltx = fmaxf(x1, tx1), lty = fmaxf(y1, ty1);
        const float rbx = fminf(x2, tx2), rby = fminf(y2, ty2);
        const float dx = fmaxf(rbx - ltx, 0.0f);
        const float dy = fmaxf(rby - lty, 0.0f);
        const float inter  = dx * dy;
        const float area_p = (x2 - x1) * (y2 - y1);
        const float v = inter / (area_p + area_t - inter);
        if (b == 0) iou0 = v; else iou1 = v;
    }
    const int b5 = (iou1 > iou0) ? 5 : 0;     // first max wins ties

    // argmax over t[10:30] — order-preserving tree (adjacent pairing keeps
    // index sets contiguous & ordered -> exact first-max semantics, depth 5)
    float av[10]; int ak[10];
    #pragma unroll
    for (int k = 0; k < 10; ++k) {
        const float a = t[10 + 2 * k], b = t[11 + 2 * k];
        const bool g = b > a;
        av[k] = g ? b : a;
        ak[k] = 10 + 2 * k + (g ? 1 : 0);
    }
    #pragma unroll
    for (int k = 0; k < 5; ++k) {
        const bool g = av[2 * k + 1] > av[2 * k];
        av[k] = g ? av[2 * k + 1] : av[2 * k];
        ak[k] = g ? ak[2 * k + 1] : ak[2 * k];
    }
    { const bool g = av[1] > av[0]; av[0] = g ? av[1] : av[0]; ak[0] = g ? ak[1] : ak[0]; }
    { const bool g = av[3] > av[2]; av[2] = g ? av[3] : av[2]; ak[2] = g ? ak[3] : ak[2]; }
    { const bool g = av[2] > av[0]; av[0] = g ? av[2] : av[0]; ak[0] = g ? ak[2] : ak[0]; }
    { const bool g = av[4] > av[0]; av[0] = g ? av[4] : av[0]; ak[0] = g ? ak[4] : ak[0]; }
    const int   kcol = ak[0];
    const float tmax = av[0];     // == t[kcol]

    const bool obj = (tc == 1.0f);
    const bool noo = (tc == 0.0f);

    const float dk = p[kcol]   - tmax;
    const float dc = p[b5 + 4] - t[b5 + 4];
    const float d0 = p[b5 + 0] - t[b5 + 0];
    const float d1 = p[b5 + 1] - t[b5 + 1];
    const float d2 = p[b5 + 2] - t[b5 + 2];
    const float d3 = p[b5 + 3] - t[b5 + 3];
    const float d4 = p[4] - tc;
    const float d9 = p[9] - t[9];

    float ax = 0.0f, ay = 0.0f, az = 0.0f, aw = 0.0f;
    if (obj) {
        ax = dk * dk;                                   // cls
        ay = dc * dc;                                   // conf
        az = d0 * d0 + d1 * d1 + d2 * d2 + d3 * d3;     // center+wh
    }
    if (noo) aw = d4 * d4 + d9 * d9;                    // noobj

    // ---- block reduce ----
    #pragma unroll
    for (int o = 16; o > 0; o >>= 1) {
        ax += __shfl_down_sync(0xffffffffu, ax, o);
        ay += __shfl_down_sync(0xffffffffu, ay, o);
        az += __shfl_down_sync(0xffffffffu, az, o);
        aw += __shfl_down_sync(0xffffffffu, aw, o);
    }
    __shared__ float4 wsum[BLK / 32];
    __shared__ bool s_last;
    if ((tid & 31) == 0) wsum[tid >> 5] = make_float4(ax, ay, az, aw);
    __syncthreads();
    if (tid == 0) {
        float4 sv = wsum[0];
        #pragma unroll
        for (int w = 1; w < BLK / 32; ++w) {
            sv.x += wsum[w].x; sv.y += wsum[w].y;
            sv.z += wsum[w].z; sv.w += wsum[w].w;
        }
        // relaxed fp64 RED (fire-and-forget, no fence)
        atomicAdd(&g_acc[0], (double)sv.x);
        atomicAdd(&g_acc[1], (double)sv.y);
        atomicAdd(&g_acc[2], (double)sv.z);
        atomicAdd(&g_acc[3], (double)sv.w);
        // acq_rel counter: release our REDs, acquire everyone else's
        unsigned int prev;
        asm volatile("atom.acq_rel.gpu.global.add.u32 %0, [%1], 1;"
                     : "=r"(prev) : "l"(&g_count) : "memory");
        s_last = (prev == (unsigned int)(NTILE - 1));
    }
    __syncthreads();
    if (!s_last) return;

    // ---- last block: trivial finalize (4 doubles from L2) ----
    if (tid == 0) {
        const double a0 = __ldcg(&g_acc[0]);
        const double a1 = __ldcg(&g_acc[1]);
        const double a2 = __ldcg(&g_acc[2]);
        const double a3 = __ldcg(&g_acc[3]);
        const float cls = (float)(5.0 * a0);   // lambda_coord
        const float cnf = (float)(5.0 * a1);
        const float cwh = (float)(5.0 * a2);
        const float nob = (float)(0.5 * a3);   // lambda_noobj
        out[0] = cls;
        out[1] = cnf;
        out[2] = cwh;
        out[3] = nob + cls + cnf + cwh;        // total
        // reset for next graph replay
        g_acc[0] = 0.0; g_acc[1] = 0.0; g_acc[2] = 0.0; g_acc[3] = 0.0;
        g_count = 0;
    }
}

extern "C" void kernel_launch(void* const* d_in, const int* in_sizes, int n_in,
                              void* d_out, int out_size)
{
    const float* P = (const float*)d_in[0];   // predictions [B,S,S,30] fp32
    const float* T = (const float*)d_in[1];   // targets     [B,S,S,30] fp32
    float* out = (float*)d_out;               // [cls, conf, center+wh, total]

    yolo_fused<<<NTILE, BLK>>>(P, T, out);
}

// round 11
// speedup vs baseline: 1.0067x; 1.0067x over previous
#include <cuda_runtime.h>
#include <cuda_bf16.h>
#include <cstdint>

// YOLOv1 loss — single kernel, R1's proven streaming structure (36.8us = the
// measured memory wall for this pattern) + ZERO-WAIT epilogue:
//   workers: 4x relaxed RED.ADD.F64 + red.release counter (fire-and-forget,
//            no return, no fence, no block wait — exits like R1 did)
//   block 6272: dedicated spinner — polls counter, fence.acquire, finalizes.

#define NCELL  (16384 * 7 * 7)       // 802816
#define BLK    128
#define TILE   128                   // cells per worker block
#define NTILE  (NCELL / TILE)        // 6272 worker blocks
#define TFL    (TILE * 30)           // floats per tensor per tile (3840)
#define TF4    (TFL / 4)             // float4 per tensor per tile (960)

__device__ double g_acc[4] = {0.0, 0.0, 0.0, 0.0};   // cls, conf, cwh, noobj
__device__ unsigned int g_count = 0;

__global__ __launch_bounds__(BLK) void yolo_fused(const float* __restrict__ P,
                                                  const float* __restrict__ T,
                                                  float* __restrict__ out)
{
    // ---------------- spinner block: finalize when all workers done --------
    if (blockIdx.x == NTILE) {
        if (threadIdx.x == 0) {
            unsigned int c;
            for (;;) {
                asm volatile("ld.global.cg.u32 %0, [%1];"
                             : "=r"(c) : "l"(&g_count) : "memory");
                if (c >= (unsigned int)NTILE) break;
                __nanosleep(256);
            }
            asm volatile("fence.acquire.gpu;" ::: "memory");
            const double a0 = __ldcg(&g_acc[0]);
            const double a1 = __ldcg(&g_acc[1]);
            const double a2 = __ldcg(&g_acc[2]);
            const double a3 = __ldcg(&g_acc[3]);
            const float cls = (float)(5.0 * a0);   // lambda_coord
            const float cnf = (float)(5.0 * a1);
            const float cwh = (float)(5.0 * a2);
            const float nob = (float)(0.5 * a3);   // lambda_noobj
            out[0] = cls;
            out[1] = cnf;
            out[2] = cwh;
            out[3] = nob + cls + cnf + cwh;        // total
            // reset for next graph replay (kernel boundary orders these)
            g_acc[0] = 0.0; g_acc[1] = 0.0; g_acc[2] = 0.0; g_acc[3] = 0.0;
            g_count = 0;
        }
        return;
    }

    // ---------------- worker blocks: exactly R1's streaming ----------------
    __shared__ float SP[TFL];
    __shared__ float ST[TFL];
    const int tid = threadIdx.x;
    const float CELL = 1.0f / 7.0f;

    const size_t base = (size_t)blockIdx.x * TFL;
    const float4* gp = (const float4*)(P + base);
    const float4* gt = (const float4*)(T + base);
    float4* sp4 = (float4*)SP;
    float4* st4 = (float4*)ST;
    #pragma unroll
    for (int i = 0; i < (TF4 + BLK - 1) / BLK; ++i) {
        int idx = tid + i * BLK;
        if (idx < TF4) { sp4[idx] = gp[idx]; st4[idx] = gt[idx]; }
    }
    __syncthreads();

    const float* p = SP + tid * 30;
    const float* t = ST + tid * 30;

    const float t0 = t[0], t1 = t[1], t2 = t[2], t3 = t[3], tc = t[4];

    // target corners — faithful to the reference's in-place bug:
    //   xy1 = xy*CELL - wh*0.5 ;  xy2 = xy1*CELL + wh*0.5
    const float twx = t2 * t2, twy = t3 * t3;
    const float tx1 = t0 * CELL - 0.5f * twx;
    const float ty1 = t1 * CELL - 0.5f * twy;
    const float tx2 = tx1 * CELL + 0.5f * twx;
    const float ty2 = ty1 * CELL + 0.5f * twy;
    const float area_t = (tx2 - tx1) * (ty2 - ty1);

    float iou0, iou1;
    #pragma unroll
    for (int b = 0; b < 2; ++b) {
        const float px = p[b * 5 + 0], py = p[b * 5 + 1];
        const float pw = p[b * 5 + 2], ph = p[b * 5 + 3];
        const float pwx = pw * pw, pwy = ph * ph;
        const float x1 = px * CELL - 0.5f * pwx;
        const float y1 = py * CELL - 0.5f * pwy;
        const float x2 = x1 * CELL + 0.5f * pwx;
        const float y2 = y1 * CELL + 0.5f * pwy;
        const float ltx = fmaxf(x1, tx1), lty = fmaxf(y1, ty1);
        const float rbx = fminf(x2, tx2), rby = fminf(y2, ty2);
        const float dx = fmaxf(rbx - ltx, 0.0f);
        const float dy = fmaxf(rby - lty, 0.0f);
        const float inter  = dx * dy;
        const float area_p = (x2 - x1) * (y2 - y1);
        const float v = inter / (area_p + area_t - inter);
        if (b == 0) iou0 = v; else iou1 = v;
    }
    const int b5 = (iou1 > iou0) ? 5 : 0;     // first max wins ties

    // argmax over t[10:30] — order-preserving tree (adjacent pairing keeps
    // index sets contiguous & ordered -> exact first-max semantics, depth 5)
    float av[10]; int ak[10];
    #pragma unroll
    for (int k = 0; k < 10; ++k) {
        const float a = t[10 + 2 * k], b = t[11 + 2 * k];
        const bool g = b > a;
        av[k] = g ? b : a;
        ak[k] = 10 + 2 * k + (g ? 1 : 0);
    }
    #pragma unroll
    for (int k = 0; k < 5; ++k) {
        const bool g = av[2 * k + 1] > av[2 * k];
        av[k] = g ? av[2 * k + 1] : av[2 * k];
        ak[k] = g ? ak[2 * k + 1] : ak[2 * k];
    }
    { const bool g = av[1] > av[0]; av[0] = g ? av[1] : av[0]; ak[0] = g ? ak[1] : ak[0]; }
    { const bool g = av[3] > av[2]; av[2] = g ? av[3] : av[2]; ak[2] = g ? ak[3] : ak[2]; }
    { const bool g = av[2] > av[0]; av[0] = g ? av[2] : av[0]; ak[0] = g ? ak[2] : ak[0]; }
    { const bool g = av[4] > av[0]; av[0] = g ? av[4] : av[0]; ak[0] = g ? ak[4] : ak[0]; }
    const int   kcol = ak[0];
    const float tmax = av[0];     // == t[kcol]

    const bool obj = (tc == 1.0f);
    const bool noo = (tc == 0.0f);

    const float dk = p[kcol]   - tmax;
    const float dc = p[b5 + 4] - t[b5 + 4];
    const float d0 = p[b5 + 0] - t[b5 + 0];
    const float d1 = p[b5 + 1] - t[b5 + 1];
    const float d2 = p[b5 + 2] - t[b5 + 2];
    const float d3 = p[b5 + 3] - t[b5 + 3];
    const float d4 = p[4] - tc;
    const float d9 = p[9] - t[9];

    float ax = 0.0f, ay = 0.0f, az = 0.0f, aw = 0.0f;
    if (obj) {
        ax = dk * dk;                                   // cls
        ay = dc * dc;                                   // conf
        az = d0 * d0 + d1 * d1 + d2 * d2 + d3 * d3;     // center+wh
    }
    if (noo) aw = d4 * d4 + d9 * d9;                    // noobj

    // ---- block reduce ----
    #pragma unroll
    for (int o = 16; o > 0; o >>= 1) {
        ax += __shfl_down_sync(0xffffffffu, ax, o);
        ay += __shfl_down_sync(0xffffffffu, ay, o);
        az += __shfl_down_sync(0xffffffffu, az, o);
        aw += __shfl_down_sync(0xffffffffu, aw, o);
    }
    __shared__ float4 wsum[BLK / 32];
    if ((tid & 31) == 0) wsum[tid >> 5] = make_float4(ax, ay, az, aw);
    __syncthreads();
    if (tid == 0) {
        float4 sv = wsum[0];
        #pragma unroll
        for (int w = 1; w < BLK / 32; ++w) {
            sv.x += wsum[w].x; sv.y += wsum[w].y;
            sv.z += wsum[w].z; sv.w += wsum[w].w;
        }
        // fire-and-forget: relaxed fp64 REDs, then RELEASE counter tick.
        // No return value, no fence, no wait — block exits immediately.
        atomicAdd(&g_acc[0], (double)sv.x);
        atomicAdd(&g_acc[1], (double)sv.y);
        atomicAdd(&g_acc[2], (double)sv.z);
        atomicAdd(&g_acc[3], (double)sv.w);
        asm volatile("red.release.gpu.global.add.u32 [%0], 1;"
                     :: "l"(&g_count) : "memory");
    }
    // no trailing syncthreads — warps retire as they arrive, like R1
}

extern "C" void kernel_launch(void* const* d_in, const int* in_sizes, int n_in,
                              void* d_out, int out_size)
{
    const float* P = (const float*)d_in[0];   // predictions [B,S,S,30] fp32
    const float* T = (const float*)d_in[1];   // targets     [B,S,S,30] fp32
    float* out = (float*)d_out;               // [cls, conf, center+wh, total]

    yolo_fused<<<NTILE + 1, BLK>>>(P, T, out);
}